// round 12
// baseline (speedup 1.0000x reference)
#include <cuda_runtime.h>
#include <cuda_bf16.h>
#include <cuda_fp16.h>
#include <math.h>
#include <stdint.h>

#define NN 50000
#define NE 600000
#define H  128
#define ED 64

// Scratch (no allocations allowed)
__device__ float  g_h[NN * H];        // LN1(x) fp32
__device__ __half g_h16[NN * H];      // LN1(x) fp16 (node A staging)
__device__ float  g_agg[NN * H];      // scatter-sum of edge_repr
__device__ float  g_deg[NN];          // edge counts per dst
__device__ float  g_gate[NE];         // gate scalar per edge
__device__ __half g_wA16[128 * 264];  // [Wself;Wagg]^T n-major, K=256 padded 264
__device__ __half g_wf1_16[256 * 136];// Wf1^T n-major, K=128 padded 136
__device__ __half g_wf2_16[128 * 264];// Wf2^T n-major, K=256 padded 264

__device__ __forceinline__ float gelu_f(float x) { return x * normcdff(x); }

// ============================ mma helpers ==================================
__device__ __forceinline__ uint32_t smem_u32(const void* p) {
    uint32_t a;
    asm("{ .reg .u64 t; cvta.to.shared.u64 t, %1; cvt.u32.u64 %0, t; }"
        : "=r"(a) : "l"(p));
    return a;
}

__device__ __forceinline__ void mma_f16(float* c, const uint32_t* a, const uint32_t* b) {
    asm volatile("mma.sync.aligned.m16n8k16.row.col.f32.f16.f16.f32 "
        "{%0,%1,%2,%3}, {%4,%5,%6,%7}, {%8,%9}, {%0,%1,%2,%3};"
        : "+f"(c[0]), "+f"(c[1]), "+f"(c[2]), "+f"(c[3])
        : "r"(a[0]), "r"(a[1]), "r"(a[2]), "r"(a[3]), "r"(b[0]), "r"(b[1]));
}

__device__ __forceinline__ void ldm_x4(uint32_t& r0, uint32_t& r1, uint32_t& r2,
                                       uint32_t& r3, uint32_t addr) {
    asm volatile("ldmatrix.sync.aligned.m8n8.x4.shared.b16 {%0,%1,%2,%3}, [%4];"
        : "=r"(r0), "=r"(r1), "=r"(r2), "=r"(r3) : "r"(addr));
}

__device__ __forceinline__ uint32_t pack_h2(float a, float b) {
    __half2 t = __floats2half2_rn(a, b);
    return *reinterpret_cast<uint32_t*>(&t);
}

// ============================ simple kernels ===============================
__global__ void zero_kernel() {
    int idx = blockIdx.x * blockDim.x + threadIdx.x;
    int stride = gridDim.x * blockDim.x;
    for (int i = idx; i < NN * H; i += stride) g_agg[i] = 0.f;
    for (int i = idx; i < NN; i += stride) g_deg[i] = 0.f;
}

// Pre-transpose + fp16-convert node weights (one-time).
__global__ void wconv_kernel(const float* __restrict__ Wself,
                             const float* __restrict__ Wagg,
                             const float* __restrict__ Wf1,
                             const float* __restrict__ Wf2) {
    int idx = blockIdx.x * blockDim.x + threadIdx.x;
    int stride = gridDim.x * blockDim.x;
    for (int i = idx; i < 128 * 256; i += stride) {
        int n = i >> 8, k = i & 255;
        float v = (k < 128) ? Wself[k * 128 + n] : Wagg[(k - 128) * 128 + n];
        g_wA16[n * 264 + k] = __float2half_rn(v);
    }
    for (int i = idx; i < 256 * 128; i += stride) {
        int n = i >> 7, k = i & 127;
        g_wf1_16[n * 136 + k] = __float2half_rn(Wf1[k * 256 + n]);
    }
    for (int i = idx; i < 128 * 256; i += stride) {
        int n = i >> 8, k = i & 255;
        g_wf2_16[n * 264 + k] = __float2half_rn(Wf2[k * 128 + n]);
    }
}

// LN1: warp per row; writes fp32 + fp16.
__global__ void ln1_kernel(const float* __restrict__ x,
                           const float* __restrict__ g,
                           const float* __restrict__ b) {
    int row = blockIdx.x * 8 + (threadIdx.x >> 5);
    if (row >= NN) return;
    int lane = threadIdx.x & 31;
    float4 v = ((const float4*)(x + (size_t)row * H))[lane];
    float s = v.x + v.y + v.z + v.w;
#pragma unroll
    for (int o = 16; o; o >>= 1) s += __shfl_xor_sync(0xffffffffu, s, o);
    float mu = s * (1.f / H);
    float dx = v.x - mu, dy = v.y - mu, dz = v.z - mu, dw = v.w - mu;
    float vs = dx * dx + dy * dy + dz * dz + dw * dw;
#pragma unroll
    for (int o = 16; o; o >>= 1) vs += __shfl_xor_sync(0xffffffffu, vs, o);
    float rs = rsqrtf(vs * (1.f / H) + 1e-5f);
    float4 gv = ((const float4*)g)[lane];
    float4 bv = ((const float4*)b)[lane];
    float4 y;
    y.x = dx * rs * gv.x + bv.x;
    y.y = dy * rs * gv.y + bv.y;
    y.z = dz * rs * gv.z + bv.z;
    y.w = dw * rs * gv.w + bv.w;
    ((float4*)(g_h + (size_t)row * H))[lane] = y;
    uint2 h;
    h.x = pack_h2(y.x, y.y);
    h.y = pack_h2(y.z, y.w);
    ((uint2*)(g_h16 + (size_t)row * H))[lane] = h;
}

__global__ void deg_kernel(const int* __restrict__ dst) {
    int i = blockIdx.x * blockDim.x + threadIdx.x;
    if (i < NE) atomicAdd(&g_deg[dst[i]], 1.f);
}

// ============================ gate edge kernel (round-7) ===================
#define G_SRC   0
#define G_DST   768
#define G_ACC   1536
#define G_BG1   2304
#define G_WG2   2816
#define G_WH    3328
#define G_A0    (G_WH + 83968)
#define G_A1    (G_A0 + 27648)
#define G_TOTAL (G_A1 + 27648)
#define G_NT    3125

__global__ __launch_bounds__(384, 1) void gate_edge_kernel(
    const int* __restrict__ esrc, const int* __restrict__ edst,
    const float* __restrict__ emb,
    const float* __restrict__ Wg1, const float* __restrict__ bg1,
    const float* __restrict__ Wg2, const float* __restrict__ bg2)
{
    extern __shared__ char sm[];
    int tid = threadIdx.x, lane = tid & 31, wid = tid >> 5;
    int warp_m = wid >> 1, warp_n = wid & 1;
    int* sSrc = (int*)(sm + G_SRC);
    int* sDst = (int*)(sm + G_DST);
    float* sAcc = (float*)(sm + G_ACC);
    float* sBg1 = (float*)(sm + G_BG1);
    float* sWg2 = (float*)(sm + G_WG2);
    uint32_t sb = smem_u32(sm);

    if (tid < 128) { sBg1[tid] = bg1[tid]; sWg2[tid] = Wg2[tid]; }
    for (int idx = tid; idx < 320 * 128; idx += 384) {
        int k = idx >> 7, n = idx & 127;
        ((__half*)(sm + G_WH))[n * 328 + k] = __float2half_rn(Wg1[idx]);
    }
    __syncthreads();
    float bg2v = bg2[0];

    int rr = lane & 7, grp = lane >> 3;
    uint32_t aA_rel = (uint32_t)(warp_m * 32 + rr + (grp & 1) * 8) * 144
                    + (uint32_t)(grp >> 1) * 16;
    uint32_t aB = sb + G_WH + (uint32_t)(warp_n * 64 + rr + (grp >> 1) * 8) * 656
                + (uint32_t)(grp & 1) * 16;

    int prow = tid >> 4, pkq = tid & 15;

    for (int t = blockIdx.x; t < G_NT; t += gridDim.x) {
        int e0 = t * 192;
        if (tid < 192) {
            int e = e0 + tid;
            sSrc[tid] = esrc[e]; sDst[tid] = edst[e];
        }
        __syncthreads();

        float acc[2][8][4];
#pragma unroll
        for (int i = 0; i < 2; i++)
#pragma unroll
            for (int j = 0; j < 8; j++)
#pragma unroll
                for (int q = 0; q < 4; q++) acc[i][j][q] = 0.f;

        float4 pf[8];
#pragma unroll
        for (int it = 0; it < 8; it++) {
            int row = prow + it * 24;
            pf[it] = ((const float4*)(g_h + (size_t)sDst[row] * H))[pkq];
        }

#pragma unroll 1
        for (int c = 0; c < 5; c++) {
            uint32_t abase = (c & 1) ? (uint32_t)G_A1 : (uint32_t)G_A0;
            char* smA = sm + abase;
#pragma unroll
            for (int it = 0; it < 8; it++) {
                int row = prow + it * 24;
                uint32_t h0 = pack_h2(pf[it].x, pf[it].y);
                uint32_t h1 = pack_h2(pf[it].z, pf[it].w);
                *(uint2*)(smA + row * 144 + pkq * 8) = make_uint2(h0, h1);
            }
            if (c < 4) {
                int cn = c + 1;
#pragma unroll
                for (int it = 0; it < 8; it++) {
                    int row = prow + it * 24;
                    const float* p;
                    if (cn == 1)      p = g_h + (size_t)sDst[row] * H + 64;
                    else if (cn == 2) p = g_h + (size_t)sSrc[row] * H;
                    else if (cn == 3) p = g_h + (size_t)sSrc[row] * H + 64;
                    else              p = emb + (size_t)(e0 + row) * ED;
                    pf[it] = ((const float4*)p)[pkq];
                }
            }
            __syncthreads();
            uint32_t aA = sb + abase + aA_rel;
            uint32_t kgb = (uint32_t)c << 7;
#pragma unroll
            for (int kk = 0; kk < 4; kk++) {
                uint32_t ah[2][4], bh[8][2];
#pragma unroll
                for (int mt = 0; mt < 2; mt++) {
                    uint32_t ad = aA + mt * (16 * 144) + kk * 32;
                    ldm_x4(ah[mt][0], ah[mt][1], ah[mt][2], ah[mt][3], ad);
                }
#pragma unroll
                for (int p4 = 0; p4 < 4; p4++) {
                    uint32_t bd = aB + p4 * (16 * 656) + kgb + kk * 32;
                    ldm_x4(bh[2 * p4][0], bh[2 * p4][1],
                           bh[2 * p4 + 1][0], bh[2 * p4 + 1][1], bd);
                }
#pragma unroll
                for (int mt = 0; mt < 2; mt++)
#pragma unroll
                    for (int nt = 0; nt < 8; nt++)
                        mma_f16(acc[mt][nt], ah[mt], bh[nt]);
            }
            __syncthreads();
        }

        if (tid < 192) sAcc[tid] = 0.f;
        __syncthreads();
#pragma unroll
        for (int mt = 0; mt < 2; mt++)
#pragma unroll
            for (int rh = 0; rh < 2; rh++) {
                int R = warp_m * 32 + mt * 16 + (lane >> 2) + rh * 8;
                float part = 0.f;
#pragma unroll
                for (int nt = 0; nt < 8; nt++) {
                    int C0 = warp_n * 64 + nt * 8 + (lane & 3) * 2;
                    part += gelu_f(acc[mt][nt][rh * 2 + 0] + sBg1[C0]) * sWg2[C0];
                    part += gelu_f(acc[mt][nt][rh * 2 + 1] + sBg1[C0 + 1]) * sWg2[C0 + 1];
                }
                part += __shfl_xor_sync(0xffffffffu, part, 1);
                part += __shfl_xor_sync(0xffffffffu, part, 2);
                if ((lane & 3) == 0) atomicAdd(&sAcc[R], part);
            }
        __syncthreads();
        if (tid < 192) {
            g_gate[e0 + tid] = 1.f / (1.f + expf(-(sAcc[tid] + bg2v)));
        }
        __syncthreads();
    }
}

// ============================ msg edge kernel (round-7) ====================
#define M_SRC   0
#define M_DST   384
#define M_BM1   768
#define M_BM2   1280
#define M_W1H   1792
#define M_W2H   (M_W1H + 51200)
#define M_UN    (M_W2H + 34816)
#define M_A10   (M_UN)
#define M_A11   (M_UN + 13824)
#define M_HH    (M_UN)
#define M_TOTAL (M_UN + 27648)
#define M_NT    6250

__global__ __launch_bounds__(384, 1) void msg_edge_kernel(
    const int* __restrict__ esrc, const int* __restrict__ edst,
    const float* __restrict__ emb,
    const float* __restrict__ Wm1, const float* __restrict__ bm1,
    const float* __restrict__ Wm2, const float* __restrict__ bm2,
    float* __restrict__ er_out)
{
    extern __shared__ char sm[];
    int tid = threadIdx.x, lane = tid & 31, wid = tid >> 5;
    int warp_m = wid >> 2, warp_n = wid & 3;
    int* sSrc = (int*)(sm + M_SRC);
    int* sDst = (int*)(sm + M_DST);
    float* sBm1 = (float*)(sm + M_BM1);
    float* sBm2 = (float*)(sm + M_BM2);
    uint32_t sb = smem_u32(sm);

    if (tid < 128) { sBm1[tid] = bm1[tid]; sBm2[tid] = bm2[tid]; }
    for (int idx = tid; idx < 192 * 128; idx += 384) {
        int k = idx >> 7, n = idx & 127;
        ((__half*)(sm + M_W1H))[n * 200 + k] = __float2half_rn(Wm1[idx]);
    }
    for (int idx = tid; idx < 128 * 128; idx += 384) {
        int k = idx >> 7, n = idx & 127;
        ((__half*)(sm + M_W2H))[n * 136 + k] = __float2half_rn(Wm2[idx]);
    }
    __syncthreads();

    int rr = lane & 7, grp = lane >> 3;
    uint32_t aA1_rel = (uint32_t)(warp_m * 32 + rr + (grp & 1) * 8) * 144
                     + (uint32_t)(grp >> 1) * 16;
    uint32_t aH = sb + M_HH + (uint32_t)(warp_m * 32 + rr + (grp & 1) * 8) * 272
                + (uint32_t)(grp >> 1) * 16;
    uint32_t aW1 = sb + M_W1H + (uint32_t)(warp_n * 32 + rr + (grp >> 1) * 8) * 400
                 + (uint32_t)(grp & 1) * 16;
    uint32_t aW2 = sb + M_W2H + (uint32_t)(warp_n * 32 + rr + (grp >> 1) * 8) * 272
                 + (uint32_t)(grp & 1) * 16;

    int prow = tid >> 4, pkq = tid & 15;

    for (int t = blockIdx.x; t < M_NT; t += gridDim.x) {
        int e0 = t * 96;
        if (tid < 96) { sSrc[tid] = esrc[e0 + tid]; sDst[tid] = edst[e0 + tid]; }
        __syncthreads();

        float acc1[2][4][4];
#pragma unroll
        for (int i = 0; i < 2; i++)
#pragma unroll
            for (int j = 0; j < 4; j++)
#pragma unroll
                for (int q = 0; q < 4; q++) acc1[i][j][q] = 0.f;

        float4 pf[4];
#pragma unroll
        for (int it = 0; it < 4; it++) {
            int row = prow + it * 24;
            pf[it] = ((const float4*)(g_h + (size_t)sSrc[row] * H))[pkq];
        }

#pragma unroll 1
        for (int c = 0; c < 3; c++) {
            uint32_t abase = (c & 1) ? (uint32_t)M_A11 : (uint32_t)M_A10;
            char* smA = sm + abase;
#pragma unroll
            for (int it = 0; it < 4; it++) {
                int row = prow + it * 24;
                uint32_t h0 = pack_h2(pf[it].x, pf[it].y);
                uint32_t h1 = pack_h2(pf[it].z, pf[it].w);
                *(uint2*)(smA + row * 144 + pkq * 8) = make_uint2(h0, h1);
            }
            if (c < 2) {
                int cn = c + 1;
#pragma unroll
                for (int it = 0; it < 4; it++) {
                    int row = prow + it * 24;
                    const float* p;
                    if (cn == 1) p = g_h + (size_t)sSrc[row] * H + 64;
                    else         p = emb + (size_t)(e0 + row) * ED;
                    pf[it] = ((const float4*)p)[pkq];
                }
            }
            __syncthreads();
            uint32_t aA1 = sb + abase + aA1_rel;
            uint32_t kgb = (uint32_t)c << 7;
#pragma unroll
            for (int kk = 0; kk < 4; kk++) {
                uint32_t ah[2][4], bh[4][2];
#pragma unroll
                for (int mt = 0; mt < 2; mt++) {
                    uint32_t ad = aA1 + mt * (16 * 144) + kk * 32;
                    ldm_x4(ah[mt][0], ah[mt][1], ah[mt][2], ah[mt][3], ad);
                }
#pragma unroll
                for (int p4 = 0; p4 < 2; p4++) {
                    uint32_t bd = aW1 + p4 * (16 * 400) + kgb + kk * 32;
                    ldm_x4(bh[2 * p4][0], bh[2 * p4][1],
                           bh[2 * p4 + 1][0], bh[2 * p4 + 1][1], bd);
                }
#pragma unroll
                for (int mt = 0; mt < 2; mt++)
#pragma unroll
                    for (int nt = 0; nt < 4; nt++)
                        mma_f16(acc1[mt][nt], ah[mt], bh[nt]);
            }
            __syncthreads();
        }

#pragma unroll
        for (int mt = 0; mt < 2; mt++)
#pragma unroll
            for (int nt = 0; nt < 4; nt++)
#pragma unroll
                for (int rh = 0; rh < 2; rh++) {
                    int R = warp_m * 32 + mt * 16 + (lane >> 2) + rh * 8;
                    int C0 = warp_n * 32 + nt * 8 + (lane & 3) * 2;
                    float v0 = gelu_f(acc1[mt][nt][rh * 2 + 0] + sBm1[C0]);
                    float v1 = gelu_f(acc1[mt][nt][rh * 2 + 1] + sBm1[C0 + 1]);
                    *(uint32_t*)(sm + M_HH + R * 272 + C0 * 2) = pack_h2(v0, v1);
                }
        __syncthreads();

        float gv[2][2]; int dnv[2][2];
#pragma unroll
        for (int mt = 0; mt < 2; mt++)
#pragma unroll
            for (int rh = 0; rh < 2; rh++) {
                int R = warp_m * 32 + mt * 16 + (lane >> 2) + rh * 8;
                gv[mt][rh] = g_gate[e0 + R];
                dnv[mt][rh] = sDst[R];
            }

        float acc2[2][4][4];
#pragma unroll
        for (int i = 0; i < 2; i++)
#pragma unroll
            for (int j = 0; j < 4; j++)
#pragma unroll
                for (int q = 0; q < 4; q++) acc2[i][j][q] = 0.f;

#pragma unroll
        for (int kk = 0; kk < 8; kk++) {
            uint32_t ah[2][4], bh[4][2];
#pragma unroll
            for (int mt = 0; mt < 2; mt++) {
                uint32_t ad = aH + mt * (16 * 272) + kk * 32;
                ldm_x4(ah[mt][0], ah[mt][1], ah[mt][2], ah[mt][3], ad);
            }
#pragma unroll
            for (int p4 = 0; p4 < 2; p4++) {
                uint32_t bd = aW2 + p4 * (16 * 272) + kk * 32;
                ldm_x4(bh[2 * p4][0], bh[2 * p4][1],
                       bh[2 * p4 + 1][0], bh[2 * p4 + 1][1], bd);
            }
#pragma unroll
            for (int mt = 0; mt < 2; mt++)
#pragma unroll
                for (int nt = 0; nt < 4; nt++)
                    mma_f16(acc2[mt][nt], ah[mt], bh[nt]);
        }

#pragma unroll
        for (int mt = 0; mt < 2; mt++)
#pragma unroll
            for (int rh = 0; rh < 2; rh++) {
                int R = warp_m * 32 + mt * 16 + (lane >> 2) + rh * 8;
                int e = e0 + R;
                float gvv = gv[mt][rh];
                int dn = dnv[mt][rh];
#pragma unroll
                for (int nt = 0; nt < 4; nt++) {
                    int C0 = warp_n * 32 + nt * 8 + (lane & 3) * 2;
                    float o0 = gvv * (acc2[mt][nt][rh * 2 + 0] + sBm2[C0]);
                    float o1 = gvv * (acc2[mt][nt][rh * 2 + 1] + sBm2[C0 + 1]);
                    float2 ov = make_float2(o0, o1);
                    *(float2*)(er_out + (size_t)e * H + C0) = ov;
                    asm volatile("red.global.add.v2.f32 [%0], {%1,%2};"
                                 :: "l"(g_agg + (size_t)dn * H + C0),
                                    "f"(o0), "f"(o1) : "memory");
                }
            }
        __syncthreads();
    }
}

// ============================ node kernel (fp16 mma) =======================
// 64 nodes/block, 256 threads, 8 warps = 2M x 4N.
// Phase A: [h | agg/deg] (K=256) @ WA -> out (+x, +biases)
// Phase B: LN2(out) @ Wf1 (N=256) -> gelu -> F1
// Phase C: F1 (K=256) @ Wf2 -> + out -> global
#define N_INV  0
#define N_BA   256
#define N_LG   768
#define N_LB   1280
#define N_BF1  1792
#define N_BF2  2816
#define N_W    3328                    // 69632 max (Wf1)
#define N_A    72960                   // 64 x 528B = 33792 (aliased by F1)
#define N_OUT  106752                  // 64 x 128 fp32 = 32768
#define N_LN   139520                  // 64 x 272B = 17408
#define N_TOTAL 156928

__global__ __launch_bounds__(256, 1) void node_kernel(
    const float* __restrict__ x,
    const float* __restrict__ bself, const float* __restrict__ bagg,
    const float* __restrict__ ln2g,  const float* __restrict__ ln2b,
    const float* __restrict__ bf1,   const float* __restrict__ bf2,
    float* __restrict__ outp)
{
    extern __shared__ char sm[];
    int tid = threadIdx.x, lane = tid & 31, wid = tid >> 5;
    int wm = wid >> 2, wn = wid & 3;   // wm 0..1, wn 0..3
    float* sInv = (float*)(sm + N_INV);
    float* sBA  = (float*)(sm + N_BA);
    float* sLG  = (float*)(sm + N_LG);
    float* sLB  = (float*)(sm + N_LB);
    float* sBF1 = (float*)(sm + N_BF1);
    float* sBF2 = (float*)(sm + N_BF2);
    float* sOut = (float*)(sm + N_OUT);
    uint32_t sb = smem_u32(sm);
    int n0 = blockIdx.x * 64;

    if (tid < 64) {
        int n = n0 + tid;
        float d = (n < NN) ? g_deg[n] : 1.f;
        sInv[tid] = 1.f / fmaxf(d, 1.f);
    }
    if (tid < 128) {
        sBA[tid] = bself[tid] + bagg[tid];
        sLG[tid] = ln2g[tid]; sLB[tid] = ln2b[tid];
        sBF2[tid] = bf2[tid];
    }
    sBF1[tid] = bf1[tid];
    __syncthreads();

    // stage A: h16 copy (k<128) + agg*inv convert (k>=128); stage WA
    for (int idx = tid; idx < 64 * 16; idx += 256) {
        int row = idx >> 4, w = idx & 15;
        int n = n0 + row; if (n >= NN) n = NN - 1;
        *(uint4*)(sm + N_A + row * 528 + w * 16) =
            ((const uint4*)(g_h16 + (size_t)n * H))[w];
    }
    for (int idx = tid; idx < 64 * 64; idx += 256) {
        int row = idx >> 6, k2 = idx & 63;
        int n = n0 + row; if (n >= NN) n = NN - 1;
        float2 f = ((const float2*)(g_agg + (size_t)n * H))[k2];
        float iv = sInv[row];
        *(uint32_t*)(sm + N_A + row * 528 + 256 + k2 * 4) = pack_h2(f.x * iv, f.y * iv);
    }
    for (int idx = tid; idx < 128 * 33; idx += 256) {
        int row = idx / 33, w = idx - row * 33;
        *(uint4*)(sm + N_W + row * 528 + w * 16) =
            *(const uint4*)((const char*)g_wA16 + row * 528 + w * 16);
    }
    __syncthreads();

    int rr = lane & 7, grp = lane >> 3;
    uint32_t aA = sb + N_A + (uint32_t)(wm * 32 + rr + (grp & 1) * 8) * 528
                + (uint32_t)(grp >> 1) * 16;
    uint32_t aLn = sb + N_LN + (uint32_t)(wm * 32 + rr + (grp & 1) * 8) * 272
                 + (uint32_t)(grp >> 1) * 16;
    uint32_t aW528 = sb + N_W + (uint32_t)(wn * 32 + rr + (grp >> 1) * 8) * 528
                   + (uint32_t)(grp & 1) * 16;
    uint32_t aW272 = sb + N_W + (uint32_t)(wn * 64 + rr + (grp >> 1) * 8) * 272
                   + (uint32_t)(grp & 1) * 16;

    // -------- Phase A --------
    float accA[2][4][4];
#pragma unroll
    for (int i = 0; i < 2; i++)
#pragma unroll
        for (int j = 0; j < 4; j++)
#pragma unroll
            for (int q = 0; q < 4; q++) accA[i][j][q] = 0.f;
#pragma unroll
    for (int kk = 0; kk < 16; kk++) {
        uint32_t ah[2][4], bh[4][2];
#pragma unroll
        for (int mt = 0; mt < 2; mt++) {
            uint32_t ad = aA + mt * (16 * 528) + kk * 32;
            ldm_x4(ah[mt][0], ah[mt][1], ah[mt][2], ah[mt][3], ad);
        }
#pragma unroll
        for (int p4 = 0; p4 < 2; p4++) {
            uint32_t bd = aW528 + p4 * (16 * 528) + kk * 32;
            ldm_x4(bh[2 * p4][0], bh[2 * p4][1],
                   bh[2 * p4 + 1][0], bh[2 * p4 + 1][1], bd);
        }
#pragma unroll
        for (int mt = 0; mt < 2; mt++)
#pragma unroll
            for (int nt = 0; nt < 4; nt++)
                mma_f16(accA[mt][nt], ah[mt], bh[nt]);
    }
    // epilogue A: out = x + acc + (bself+bagg)
#pragma unroll
    for (int mt = 0; mt < 2; mt++)
#pragma unroll
        for (int rh = 0; rh < 2; rh++) {
            int R = wm * 32 + mt * 16 + (lane >> 2) + rh * 8;
            int n = n0 + R; if (n >= NN) n = NN - 1;
#pragma unroll
            for (int nt = 0; nt < 4; nt++) {
                int C0 = wn * 32 + nt * 8 + (lane & 3) * 2;
                float2 xv = *(const float2*)(x + (size_t)n * H + C0);
                float2 o;
                o.x = xv.x + accA[mt][nt][rh * 2 + 0] + sBA[C0];
                o.y = xv.y + accA[mt][nt][rh * 2 + 1] + sBA[C0 + 1];
                *(float2*)(sOut + R * 128 + C0) = o;
            }
        }
    __syncthreads();

    // -------- LN2 -> sLn (fp16) ; stage Wf1 --------
#pragma unroll
    for (int p = 0; p < 8; p++) {
        int r = wid * 8 + p;
        float v[4]; float s = 0.f;
#pragma unroll
        for (int i = 0; i < 4; i++) { v[i] = sOut[r * 128 + lane + 32 * i]; s += v[i]; }
#pragma unroll
        for (int o = 16; o; o >>= 1) s += __shfl_xor_sync(0xffffffffu, s, o);
        float mu = s * (1.f / H);
        float vs = 0.f;
#pragma unroll
        for (int i = 0; i < 4; i++) { float d = v[i] - mu; vs += d * d; }
#pragma unroll
        for (int o = 16; o; o >>= 1) vs += __shfl_xor_sync(0xffffffffu, vs, o);
        float rs = rsqrtf(vs * (1.f / H) + 1e-5f);
#pragma unroll
        for (int i = 0; i < 4; i++) {
            int c = lane + 32 * i;
            float y = (v[i] - mu) * rs * sLG[c] + sLB[c];
            ((__half*)(sm + N_LN))[r * 136 + c] = __float2half_rn(y);
        }
    }
    for (int idx = tid; idx < 256 * 17; idx += 256) {
        int row = idx / 17, w = idx - row * 17;
        *(uint4*)(sm + N_W + row * 272 + w * 16) =
            *(const uint4*)((const char*)g_wf1_16 + row * 272 + w * 16);
    }
    __syncthreads();

    // -------- Phase B: N=256, warp tile 32x64 --------
    float accF[2][8][4];
#pragma unroll
    for (int i = 0; i < 2; i++)
#pragma unroll
        for (int j = 0; j < 8; j++)
#pragma unroll
            for (int q = 0; q < 4; q++) accF[i][j][q] = 0.f;
#pragma unroll
    for (int kk = 0; kk < 8; kk++) {
        uint32_t ah[2][4], bh[8][2];
#pragma unroll
        for (int mt = 0; mt < 2; mt++) {
            uint32_t ad = aLn + mt * (16 * 272) + kk * 32;
            ldm_x4(ah[mt][0], ah[mt][1], ah[mt][2], ah[mt][3], ad);
        }
#pragma unroll
        for (int p4 = 0; p4 < 4; p4++) {
            uint32_t bd = aW272 + p4 * (16 * 272) + kk * 32;
            ldm_x4(bh[2 * p4][0], bh[2 * p4][1],
                   bh[2 * p4 + 1][0], bh[2 * p4 + 1][1], bd);
        }
#pragma unroll
        for (int mt = 0; mt < 2; mt++)
#pragma unroll
            for (int nt = 0; nt < 8; nt++)
                mma_f16(accF[mt][nt], ah[mt], bh[nt]);
    }
    // epilogue B: gelu -> F1 fp16 (aliases N_A; A dead)
#pragma unroll
    for (int mt = 0; mt < 2; mt++)
#pragma unroll
        for (int nt = 0; nt < 8; nt++)
#pragma unroll
            for (int rh = 0; rh < 2; rh++) {
                int R = wm * 32 + mt * 16 + (lane >> 2) + rh * 8;
                int C0 = wn * 64 + nt * 8 + (lane & 3) * 2;
                float v0 = gelu_f(accF[mt][nt][rh * 2 + 0] + sBF1[C0]);
                float v1 = gelu_f(accF[mt][nt][rh * 2 + 1] + sBF1[C0 + 1]);
                *(uint32_t*)(sm + N_A + R * 528 + C0 * 2) = pack_h2(v0, v1);
            }
    __syncthreads();

    // stage Wf2
    for (int idx = tid; idx < 128 * 33; idx += 256) {
        int row = idx / 33, w = idx - row * 33;
        *(uint4*)(sm + N_W + row * 528 + w * 16) =
            *(const uint4*)((const char*)g_wf2_16 + row * 528 + w * 16);
    }
    __syncthreads();

    // -------- Phase C: K=256 --------
    float accC[2][4][4];
#pragma unroll
    for (int i = 0; i < 2; i++)
#pragma unroll
        for (int j = 0; j < 4; j++)
#pragma unroll
            for (int q = 0; q < 4; q++) accC[i][j][q] = 0.f;
#pragma unroll
    for (int kk = 0; kk < 16; kk++) {
        uint32_t ah[2][4], bh[4][2];
#pragma unroll
        for (int mt = 0; mt < 2; mt++) {
            uint32_t ad = aA + mt * (16 * 528) + kk * 32;
            ldm_x4(ah[mt][0], ah[mt][1], ah[mt][2], ah[mt][3], ad);
        }
#pragma unroll
        for (int p4 = 0; p4 < 2; p4++) {
            uint32_t bd = aW528 + p4 * (16 * 528) + kk * 32;
            ldm_x4(bh[2 * p4][0], bh[2 * p4][1],
                   bh[2 * p4 + 1][0], bh[2 * p4 + 1][1], bd);
        }
#pragma unroll
        for (int mt = 0; mt < 2; mt++)
#pragma unroll
            for (int nt = 0; nt < 4; nt++)
                mma_f16(accC[mt][nt], ah[mt], bh[nt]);
    }
    // epilogue C: final = out + acc + bf2
#pragma unroll
    for (int mt = 0; mt < 2; mt++)
#pragma unroll
        for (int rh = 0; rh < 2; rh++) {
            int R = wm * 32 + mt * 16 + (lane >> 2) + rh * 8;
            int n = n0 + R;
            if (n < NN) {
#pragma unroll
                for (int nt = 0; nt < 4; nt++) {
                    int C0 = wn * 32 + nt * 8 + (lane & 3) * 2;
                    float2 o;
                    o.x = sOut[R * 128 + C0] + accC[mt][nt][rh * 2 + 0] + sBF2[C0];
                    o.y = sOut[R * 128 + C0 + 1] + accC[mt][nt][rh * 2 + 1] + sBF2[C0 + 1];
                    *(float2*)(outp + (size_t)n * H + C0) = o;
                }
            }
        }
}

// ===========================================================================
extern "C" void kernel_launch(void* const* d_in, const int* in_sizes, int n_in,
                              void* d_out, int out_size) {
    const float* x     = (const float*)d_in[0];
    const int*   esrc  = (const int*)d_in[1];
    const int*   edst  = (const int*)d_in[2];
    const float* emb   = (const float*)d_in[3];
    const float* ln1g  = (const float*)d_in[4];
    const float* ln1b  = (const float*)d_in[5];
    const float* Wself = (const float*)d_in[6];
    const float* bself = (const float*)d_in[7];
    const float* Wm1   = (const float*)d_in[8];
    const float* bm1   = (const float*)d_in[9];
    const float* Wm2   = (const float*)d_in[10];
    const float* bm2   = (const float*)d_in[11];
    const float* Wg1   = (const float*)d_in[12];
    const float* bg1   = (const float*)d_in[13];
    const float* Wg2   = (const float*)d_in[14];
    const float* bg2   = (const float*)d_in[15];
    const float* Wagg  = (const float*)d_in[16];
    const float* bagg  = (const float*)d_in[17];
    const float* ln2g  = (const float*)d_in[18];
    const float* ln2b  = (const float*)d_in[19];
    const float* Wf1   = (const float*)d_in[20];
    const float* bf1   = (const float*)d_in[21];
    const float* Wf2   = (const float*)d_in[22];
    const float* bf2   = (const float*)d_in[23];

    float* outp = (float*)d_out;
    float* erp  = outp + (size_t)NN * H;

    cudaFuncSetAttribute(gate_edge_kernel, cudaFuncAttributeMaxDynamicSharedMemorySize,
                         G_TOTAL);
    cudaFuncSetAttribute(msg_edge_kernel, cudaFuncAttributeMaxDynamicSharedMemorySize,
                         M_TOTAL);
    cudaFuncSetAttribute(node_kernel, cudaFuncAttributeMaxDynamicSharedMemorySize,
                         N_TOTAL);

    zero_kernel<<<1024, 256>>>();
    wconv_kernel<<<256, 256>>>(Wself, Wagg, Wf1, Wf2);
    ln1_kernel<<<(NN + 7) / 8, 256>>>(x, ln1g, ln1b);
    deg_kernel<<<(NE + 255) / 256, 256>>>(edst);
    gate_edge_kernel<<<148, 384, G_TOTAL>>>(esrc, edst, emb, Wg1, bg1, Wg2, bg2);
    msg_edge_kernel<<<148, 384, M_TOTAL>>>(esrc, edst, emb, Wm1, bm1, Wm2, bm2, erp);
    node_kernel<<<(NN + 63) / 64, 256, N_TOTAL>>>(x, bself, bagg, ln2g, ln2b,
                                                  bf1, bf2, outp);
}

// round 13
// speedup vs baseline: 1.3150x; 1.3150x over previous
#include <cuda_runtime.h>
#include <cuda_bf16.h>
#include <cuda_fp16.h>
#include <math.h>
#include <stdint.h>

#define NN 50000
#define NE 600000
#define H  128
#define ED 64

// Scratch (no allocations allowed)
__device__ float g_h[NN * H];     // LN1(x)
__device__ float g_agg[NN * H];   // scatter-sum of edge_repr
__device__ float g_deg[NN];       // edge counts per dst

__device__ __forceinline__ float gelu_f(float x) { return x * normcdff(x); }

// ============================ mma helpers ==================================
__device__ __forceinline__ uint32_t smem_u32(const void* p) {
    uint32_t a;
    asm("{ .reg .u64 t; cvta.to.shared.u64 t, %1; cvt.u32.u64 %0, t; }"
        : "=r"(a) : "l"(p));
    return a;
}

__device__ __forceinline__ void mma_f16(float* c, const uint32_t* a, const uint32_t* b) {
    asm volatile("mma.sync.aligned.m16n8k16.row.col.f32.f16.f16.f32 "
        "{%0,%1,%2,%3}, {%4,%5,%6,%7}, {%8,%9}, {%0,%1,%2,%3};"
        : "+f"(c[0]), "+f"(c[1]), "+f"(c[2]), "+f"(c[3])
        : "r"(a[0]), "r"(a[1]), "r"(a[2]), "r"(a[3]), "r"(b[0]), "r"(b[1]));
}

__device__ __forceinline__ void ldm_x4(uint32_t& r0, uint32_t& r1, uint32_t& r2,
                                       uint32_t& r3, uint32_t addr) {
    asm volatile("ldmatrix.sync.aligned.m8n8.x4.shared.b16 {%0,%1,%2,%3}, [%4];"
        : "=r"(r0), "=r"(r1), "=r"(r2), "=r"(r3) : "r"(addr));
}

__device__ __forceinline__ uint32_t pack_h2(float a, float b) {
    __half2 t = __floats2half2_rn(a, b);
    return *reinterpret_cast<uint32_t*>(&t);
}

// ============================ simple kernels ===============================
__global__ void zero_kernel() {
    int idx = blockIdx.x * blockDim.x + threadIdx.x;
    int stride = gridDim.x * blockDim.x;
    for (int i = idx; i < NN * H; i += stride) g_agg[i] = 0.f;
    for (int i = idx; i < NN; i += stride) g_deg[i] = 0.f;
}

__global__ void ln1_kernel(const float* __restrict__ x,
                           const float* __restrict__ g,
                           const float* __restrict__ b) {
    int row = blockIdx.x * 8 + (threadIdx.x >> 5);
    if (row >= NN) return;
    int lane = threadIdx.x & 31;
    float v[4]; float s = 0.f;
#pragma unroll
    for (int i = 0; i < 4; i++) { v[i] = x[row * H + lane + 32 * i]; s += v[i]; }
#pragma unroll
    for (int o = 16; o; o >>= 1) s += __shfl_xor_sync(0xffffffffu, s, o);
    float mu = s * (1.f / H);
    float vs = 0.f;
#pragma unroll
    for (int i = 0; i < 4; i++) { float d = v[i] - mu; vs += d * d; }
#pragma unroll
    for (int o = 16; o; o >>= 1) vs += __shfl_xor_sync(0xffffffffu, vs, o);
    float rs = rsqrtf(vs * (1.f / H) + 1e-5f);
#pragma unroll
    for (int i = 0; i < 4; i++) {
        int c = lane + 32 * i;
        g_h[row * H + c] = (v[i] - mu) * rs * g[c] + b[c];
    }
}

__global__ void deg_kernel(const int* __restrict__ dst) {
    int i = blockIdx.x * blockDim.x + threadIdx.x;
    if (i < NE) atomicAdd(&g_deg[dst[i]], 1.f);
}

// ============================ fused edge kernel ============================
// 384 threads, 96-edge tiles (600000 = 96*6250), 12 warps = 3M x 4N.
// One staged A tile [hd|hs|e] (K=320) feeds BOTH the gate GEMM (all 5 chunks)
// and the msg GEMM1 (chunks 2..4). Gate scalar stays in smem.
#define F_SRC   0                      // 96 ints
#define F_DST   384
#define F_ACC   768                    // 96 floats
#define F_BG1   1152                   // 128 floats
#define F_WG2   1664
#define F_BM1   2176
#define F_BM2   2688
#define F_WG1   3200                   // 128 x 328 fp16 (656B stride) = 83968
#define F_WM1   (F_WG1 + 83968)        // 128 x 200 fp16 (400B stride) = 51200
#define F_WM2   (F_WM1 + 51200)        // 128 x 136 fp16 (272B stride) = 34816
#define F_UN    (F_WM2 + 34816)        // union region
#define F_A0    (F_UN)                 // A buf0: 96 x 72 fp16 (144B) = 13824
#define F_A1    (F_UN + 13824)         // A buf1
#define F_HH    (F_UN)                 // H: 96 x 136 fp16 (272B) = 26112
#define F_TOTAL (F_UN + 27648)         // 200832
#define F_NT    6250

__global__ __launch_bounds__(384, 1) void edge_kernel(
    const int* __restrict__ esrc, const int* __restrict__ edst,
    const float* __restrict__ emb,
    const float* __restrict__ Wg1, const float* __restrict__ bg1,
    const float* __restrict__ Wg2, const float* __restrict__ bg2,
    const float* __restrict__ Wm1, const float* __restrict__ bm1,
    const float* __restrict__ Wm2, const float* __restrict__ bm2,
    float* __restrict__ er_out)
{
    extern __shared__ char sm[];
    int tid = threadIdx.x, lane = tid & 31, wid = tid >> 5;
    int warp_m = wid >> 2, warp_n = wid & 3;  // warp_m 0..2, warp_n 0..3
    int* sSrc = (int*)(sm + F_SRC);
    int* sDst = (int*)(sm + F_DST);
    float* sAcc = (float*)(sm + F_ACC);
    float* sBg1 = (float*)(sm + F_BG1);
    float* sWg2 = (float*)(sm + F_WG2);
    float* sBm1 = (float*)(sm + F_BM1);
    float* sBm2 = (float*)(sm + F_BM2);
    uint32_t sb = smem_u32(sm);

    if (tid < 128) {
        sBg1[tid] = bg1[tid]; sWg2[tid] = Wg2[tid];
        sBm1[tid] = bm1[tid]; sBm2[tid] = bm2[tid];
    }
    for (int idx = tid; idx < 320 * 128; idx += 384) {
        int k = idx >> 7, n = idx & 127;
        ((__half*)(sm + F_WG1))[n * 328 + k] = __float2half_rn(Wg1[idx]);
    }
    for (int idx = tid; idx < 192 * 128; idx += 384) {
        int k = idx >> 7, n = idx & 127;
        ((__half*)(sm + F_WM1))[n * 200 + k] = __float2half_rn(Wm1[idx]);
    }
    for (int idx = tid; idx < 128 * 128; idx += 384) {
        int k = idx >> 7, n = idx & 127;
        ((__half*)(sm + F_WM2))[n * 136 + k] = __float2half_rn(Wm2[idx]);
    }
    __syncthreads();
    float bg2v = bg2[0];

    int rr = lane & 7, grp = lane >> 3;
    uint32_t aA_rel = (uint32_t)(warp_m * 32 + rr + (grp & 1) * 8) * 144
                    + (uint32_t)(grp >> 1) * 16;
    uint32_t aBg = sb + F_WG1 + (uint32_t)(warp_n * 32 + rr + (grp >> 1) * 8) * 656
                 + (uint32_t)(grp & 1) * 16;
    uint32_t aBm = sb + F_WM1 + (uint32_t)(warp_n * 32 + rr + (grp >> 1) * 8) * 400
                 + (uint32_t)(grp & 1) * 16;
    uint32_t aH = sb + F_HH + (uint32_t)(warp_m * 32 + rr + (grp & 1) * 8) * 272
                + (uint32_t)(grp >> 1) * 16;
    uint32_t aW2 = sb + F_WM2 + (uint32_t)(warp_n * 32 + rr + (grp >> 1) * 8) * 272
                 + (uint32_t)(grp & 1) * 16;

    int prow = tid >> 4, pkq = tid & 15;   // rows prow + it*24, it 0..3

    for (int t = blockIdx.x; t < F_NT; t += gridDim.x) {
        int e0 = t * 96;
        if (tid < 96) {
            sSrc[tid] = esrc[e0 + tid]; sDst[tid] = edst[e0 + tid];
            sAcc[tid] = 0.f;   // zero gate accumulator here (region disjoint
                               // from A/H buffers; end-of-tile barrier orders
                               // it against the previous tile's reads)
        }
        __syncthreads();

        float accG[2][4][4], accM[2][4][4];
#pragma unroll
        for (int i = 0; i < 2; i++)
#pragma unroll
            for (int j = 0; j < 4; j++)
#pragma unroll
                for (int q = 0; q < 4; q++) { accG[i][j][q] = 0.f; accM[i][j][q] = 0.f; }

        // prefetch chunk 0 (hd cols 0..63)
        float4 pf[4];
#pragma unroll
        for (int it = 0; it < 4; it++) {
            int row = prow + it * 24;
            pf[it] = ((const float4*)(g_h + (size_t)sDst[row] * H))[pkq];
        }

#pragma unroll 1
        for (int c = 0; c < 5; c++) {
            uint32_t abase = (c & 1) ? (uint32_t)F_A1 : (uint32_t)F_A0;
            char* smA = sm + abase;
#pragma unroll
            for (int it = 0; it < 4; it++) {
                int row = prow + it * 24;
                uint32_t h0 = pack_h2(pf[it].x, pf[it].y);
                uint32_t h1 = pack_h2(pf[it].z, pf[it].w);
                *(uint2*)(smA + row * 144 + pkq * 8) = make_uint2(h0, h1);
            }
            if (c < 4) {
                int cn = c + 1;
#pragma unroll
                for (int it = 0; it < 4; it++) {
                    int row = prow + it * 24;
                    const float* p;
                    if (cn == 1)      p = g_h + (size_t)sDst[row] * H + 64;
                    else if (cn == 2) p = g_h + (size_t)sSrc[row] * H;
                    else if (cn == 3) p = g_h + (size_t)sSrc[row] * H + 64;
                    else              p = emb + (size_t)(e0 + row) * ED;
                    pf[it] = ((const float4*)p)[pkq];
                }
            }
            __syncthreads();
            uint32_t aA = sb + abase + aA_rel;
            uint32_t kgb_g = (uint32_t)c << 7;
            bool do_m = (c >= 2);
            uint32_t kgb_m = (uint32_t)(c - 2) << 7;
#pragma unroll
            for (int kk = 0; kk < 4; kk++) {
                uint32_t ah[2][4], bg[4][2], bm[4][2];
#pragma unroll
                for (int mt = 0; mt < 2; mt++) {
                    uint32_t ad = aA + mt * (16 * 144) + kk * 32;
                    ldm_x4(ah[mt][0], ah[mt][1], ah[mt][2], ah[mt][3], ad);
                }
#pragma unroll
                for (int p4 = 0; p4 < 2; p4++) {
                    uint32_t bd = aBg + p4 * (16 * 656) + kgb_g + kk * 32;
                    ldm_x4(bg[2 * p4][0], bg[2 * p4][1],
                           bg[2 * p4 + 1][0], bg[2 * p4 + 1][1], bd);
                }
                if (do_m) {
#pragma unroll
                    for (int p4 = 0; p4 < 2; p4++) {
                        uint32_t bd = aBm + p4 * (16 * 400) + kgb_m + kk * 32;
                        ldm_x4(bm[2 * p4][0], bm[2 * p4][1],
                               bm[2 * p4 + 1][0], bm[2 * p4 + 1][1], bd);
                    }
                }
#pragma unroll
                for (int mt = 0; mt < 2; mt++)
#pragma unroll
                    for (int nt = 0; nt < 4; nt++) {
                        mma_f16(accG[mt][nt], ah[mt], bg[nt]);
                        if (do_m) mma_f16(accM[mt][nt], ah[mt], bm[nt]);
                    }
            }
        }

        __syncthreads();

        // gate partial reduce (gelu + dot Wg2 over this warp's 32 cols)
#pragma unroll
        for (int mt = 0; mt < 2; mt++)
#pragma unroll
            for (int rh = 0; rh < 2; rh++) {
                int R = warp_m * 32 + mt * 16 + (lane >> 2) + rh * 8;
                float part = 0.f;
#pragma unroll
                for (int nt = 0; nt < 4; nt++) {
                    int C0 = warp_n * 32 + nt * 8 + (lane & 3) * 2;
                    part += gelu_f(accG[mt][nt][rh * 2 + 0] + sBg1[C0]) * sWg2[C0];
                    part += gelu_f(accG[mt][nt][rh * 2 + 1] + sBg1[C0 + 1]) * sWg2[C0 + 1];
                }
                part += __shfl_xor_sync(0xffffffffu, part, 1);
                part += __shfl_xor_sync(0xffffffffu, part, 2);
                if ((lane & 3) == 0) atomicAdd(&sAcc[R], part);
            }

        // gelu(accM) -> H (fp16). H region overlaps dead A buffers (post-sync).
#pragma unroll
        for (int mt = 0; mt < 2; mt++)
#pragma unroll
            for (int nt = 0; nt < 4; nt++)
#pragma unroll
                for (int rh = 0; rh < 2; rh++) {
                    int R = warp_m * 32 + mt * 16 + (lane >> 2) + rh * 8;
                    int C0 = warp_n * 32 + nt * 8 + (lane & 3) * 2;
                    float v0 = gelu_f(accM[mt][nt][rh * 2 + 0] + sBm1[C0]);
                    float v1 = gelu_f(accM[mt][nt][rh * 2 + 1] + sBm1[C0 + 1]);
                    *(uint32_t*)(sm + F_HH + R * 272 + C0 * 2) = pack_h2(v0, v1);
                }
        __syncthreads();

        // gate scalar + dst per epilogue row (sAcc complete after sync)
        float gv[2][2]; int dnv[2][2];
#pragma unroll
        for (int mt = 0; mt < 2; mt++)
#pragma unroll
            for (int rh = 0; rh < 2; rh++) {
                int R = warp_m * 32 + mt * 16 + (lane >> 2) + rh * 8;
                gv[mt][rh] = 1.f / (1.f + expf(-(sAcc[R] + bg2v)));
                dnv[mt][rh] = sDst[R];
            }

        float acc2[2][4][4];
#pragma unroll
        for (int i = 0; i < 2; i++)
#pragma unroll
            for (int j = 0; j < 4; j++)
#pragma unroll
                for (int q = 0; q < 4; q++) acc2[i][j][q] = 0.f;

#pragma unroll
        for (int kk = 0; kk < 8; kk++) {
            uint32_t ah[2][4], bh[4][2];
#pragma unroll
            for (int mt = 0; mt < 2; mt++) {
                uint32_t ad = aH + mt * (16 * 272) + kk * 32;
                ldm_x4(ah[mt][0], ah[mt][1], ah[mt][2], ah[mt][3], ad);
            }
#pragma unroll
            for (int p4 = 0; p4 < 2; p4++) {
                uint32_t bd = aW2 + p4 * (16 * 272) + kk * 32;
                ldm_x4(bh[2 * p4][0], bh[2 * p4][1],
                       bh[2 * p4 + 1][0], bh[2 * p4 + 1][1], bd);
            }
#pragma unroll
            for (int mt = 0; mt < 2; mt++)
#pragma unroll
                for (int nt = 0; nt < 4; nt++)
                    mma_f16(acc2[mt][nt], ah[mt], bh[nt]);
        }

        // epilogue: er = gate * (D2 + bm2); store + scatter
#pragma unroll
        for (int mt = 0; mt < 2; mt++)
#pragma unroll
            for (int rh = 0; rh < 2; rh++) {
                int R = warp_m * 32 + mt * 16 + (lane >> 2) + rh * 8;
                int e = e0 + R;
                float gvv = gv[mt][rh];
                int dn = dnv[mt][rh];
#pragma unroll
                for (int nt = 0; nt < 4; nt++) {
                    int C0 = warp_n * 32 + nt * 8 + (lane & 3) * 2;
                    float o0 = gvv * (acc2[mt][nt][rh * 2 + 0] + sBm2[C0]);
                    float o1 = gvv * (acc2[mt][nt][rh * 2 + 1] + sBm2[C0 + 1]);
                    float2 ov = make_float2(o0, o1);
                    *(float2*)(er_out + (size_t)e * H + C0) = ov;
                    asm volatile("red.global.add.v2.f32 [%0], {%1,%2};"
                                 :: "l"(g_agg + (size_t)dn * H + C0),
                                    "f"(o0), "f"(o1) : "memory");
                }
            }
        __syncthreads();
    }
}

// ============================ node kernel ==================================
#define NODE_SMEM_BYTES (49216 * 4)

__global__ __launch_bounds__(256, 1) void node_kernel(
    const float* __restrict__ x,
    const float* __restrict__ Wself, const float* __restrict__ bself,
    const float* __restrict__ Wagg,  const float* __restrict__ bagg,
    const float* __restrict__ ln2g,  const float* __restrict__ ln2b,
    const float* __restrict__ Wf1,   const float* __restrict__ bf1,
    const float* __restrict__ Wf2,   const float* __restrict__ bf2,
    float* __restrict__ outp)
{
    extern __shared__ float smf[];
    float* sAh  = smf;
    float* sAa  = sAh + 2048;
    float* sB   = sAa + 2048;
    float* sB2  = sB + 8192;
    float* sOut = sB2 + 4096;
    float* sLn  = sOut + 8192;
    float* sF1  = sLn + 8192;
    float* sInv = sF1 + 16384;

    int tid = threadIdx.x;
    int tx = tid & 31, ty = tid >> 5;
    int n0 = blockIdx.x * 64;

    if (tid < 64) {
        int n = n0 + tid;
        float d = (n < NN) ? g_deg[n] : 1.f;
        sInv[tid] = 1.f / fmaxf(d, 1.f);
    }

    float acc[8][4];
#pragma unroll
    for (int i = 0; i < 8; i++)
#pragma unroll
        for (int j = 0; j < 4; j++) acc[i][j] = 0.f;

    for (int k0 = 0; k0 < 128; k0 += 32) {
        __syncthreads();
#pragma unroll
        for (int i = 0; i < 8; i++) {
            int lin = tid + i * 256;
            int e = lin >> 5, k = lin & 31;
            int n = n0 + e; if (n >= NN) n = NN - 1;
            sAh[e * 32 + k] = g_h[n * H + k0 + k];
            sAa[e * 32 + k] = g_agg[n * H + k0 + k] * sInv[e];
        }
#pragma unroll
        for (int i = 0; i < 16; i++) {
            int lin = tid + i * 256;
            int kk = lin >> 7, c = lin & 127;
            sB[kk * 128 + c]  = Wself[(k0 + kk) * 128 + c];
            sB2[kk * 128 + c] = Wagg[(k0 + kk) * 128 + c];
        }
        __syncthreads();
#pragma unroll 4
        for (int kk = 0; kk < 32; kk++) {
            float ah[8], aa[8];
#pragma unroll
            for (int i = 0; i < 8; i++) {
                ah[i] = sAh[(ty * 8 + i) * 32 + kk];
                aa[i] = sAa[(ty * 8 + i) * 32 + kk];
            }
            float4 bs = *(const float4*)(sB + kk * 128 + tx * 4);
            float4 ba = *(const float4*)(sB2 + kk * 128 + tx * 4);
#pragma unroll
            for (int i = 0; i < 8; i++) {
                acc[i][0] = fmaf(ah[i], bs.x, fmaf(aa[i], ba.x, acc[i][0]));
                acc[i][1] = fmaf(ah[i], bs.y, fmaf(aa[i], ba.y, acc[i][1]));
                acc[i][2] = fmaf(ah[i], bs.z, fmaf(aa[i], ba.z, acc[i][2]));
                acc[i][3] = fmaf(ah[i], bs.w, fmaf(aa[i], ba.w, acc[i][3]));
            }
        }
    }

    {
        int c0 = tx * 4;
        float4 b1 = *(const float4*)(bself + c0);
        float4 b2 = *(const float4*)(bagg + c0);
#pragma unroll
        for (int i = 0; i < 8; i++) {
            int r = ty * 8 + i;
            int n = n0 + r; if (n >= NN) n = NN - 1;
            float4 xv = *(const float4*)(x + (size_t)n * H + c0);
            float4 o;
            o.x = xv.x + acc[i][0] + b1.x + b2.x;
            o.y = xv.y + acc[i][1] + b1.y + b2.y;
            o.z = xv.z + acc[i][2] + b1.z + b2.z;
            o.w = xv.w + acc[i][3] + b1.w + b2.w;
            *(float4*)(sOut + r * 128 + c0) = o;
        }
    }
    __syncthreads();

#pragma unroll
    for (int p = 0; p < 8; p++) {
        int r = ty * 8 + p;
        float v[4]; float s = 0.f;
#pragma unroll
        for (int i = 0; i < 4; i++) { v[i] = sOut[r * 128 + tx + 32 * i]; s += v[i]; }
#pragma unroll
        for (int o = 16; o; o >>= 1) s += __shfl_xor_sync(0xffffffffu, s, o);
        float mu = s * (1.f / H);
        float vs = 0.f;
#pragma unroll
        for (int i = 0; i < 4; i++) { float d = v[i] - mu; vs += d * d; }
#pragma unroll
        for (int o = 16; o; o >>= 1) vs += __shfl_xor_sync(0xffffffffu, vs, o);
        float rs = rsqrtf(vs * (1.f / H) + 1e-5f);
#pragma unroll
        for (int i = 0; i < 4; i++) {
            int c = tx + 32 * i;
            sLn[r * 128 + c] = (v[i] - mu) * rs * ln2g[c] + ln2b[c];
        }
    }

    float accF[8][8];
#pragma unroll
    for (int i = 0; i < 8; i++)
#pragma unroll
        for (int j = 0; j < 8; j++) accF[i][j] = 0.f;

    for (int k0 = 0; k0 < 128; k0 += 32) {
        __syncthreads();
#pragma unroll
        for (int i = 0; i < 32; i++) {
            int lin = tid + i * 256;
            int kk = lin >> 8, c = lin & 255;
            sB[kk * 256 + c] = Wf1[(k0 + kk) * 256 + c];
        }
        __syncthreads();
#pragma unroll 4
        for (int kk = 0; kk < 32; kk++) {
            float a[8];
#pragma unroll
            for (int i = 0; i < 8; i++) a[i] = sLn[(ty * 8 + i) * 128 + k0 + kk];
            float4 b0 = *(const float4*)(sB + kk * 256 + tx * 4);
            float4 b1v = *(const float4*)(sB + kk * 256 + 128 + tx * 4);
#pragma unroll
            for (int i = 0; i < 8; i++) {
                accF[i][0] = fmaf(a[i], b0.x, accF[i][0]);
                accF[i][1] = fmaf(a[i], b0.y, accF[i][1]);
                accF[i][2] = fmaf(a[i], b0.z, accF[i][2]);
                accF[i][3] = fmaf(a[i], b0.w, accF[i][3]);
                accF[i][4] = fmaf(a[i], b1v.x, accF[i][4]);
                accF[i][5] = fmaf(a[i], b1v.y, accF[i][5]);
                accF[i][6] = fmaf(a[i], b1v.z, accF[i][6]);
                accF[i][7] = fmaf(a[i], b1v.w, accF[i][7]);
            }
        }
    }
    {
        int c0a = tx * 4, c0b = 128 + tx * 4;
        float4 ba = *(const float4*)(bf1 + c0a);
        float4 bb = *(const float4*)(bf1 + c0b);
#pragma unroll
        for (int i = 0; i < 8; i++) {
            int r = ty * 8 + i;
            float4 fa, fb;
            fa.x = gelu_f(accF[i][0] + ba.x); fa.y = gelu_f(accF[i][1] + ba.y);
            fa.z = gelu_f(accF[i][2] + ba.z); fa.w = gelu_f(accF[i][3] + ba.w);
            fb.x = gelu_f(accF[i][4] + bb.x); fb.y = gelu_f(accF[i][5] + bb.y);
            fb.z = gelu_f(accF[i][6] + bb.z); fb.w = gelu_f(accF[i][7] + bb.w);
            *(float4*)(sF1 + r * 256 + c0a) = fa;
            *(float4*)(sF1 + r * 256 + c0b) = fb;
        }
    }
    __syncthreads();

    float acc2[8][4];
#pragma unroll
    for (int i = 0; i < 8; i++)
#pragma unroll
        for (int j = 0; j < 4; j++) acc2[i][j] = 0.f;

    for (int k0 = 0; k0 < 256; k0 += 32) {
        __syncthreads();
#pragma unroll
        for (int i = 0; i < 16; i++) {
            int lin = tid + i * 256;
            int kk = lin >> 7, c = lin & 127;
            sB2[kk * 128 + c] = Wf2[(k0 + kk) * 128 + c];
        }
        __syncthreads();
#pragma unroll 4
        for (int kk = 0; kk < 32; kk++) {
            float a[8];
#pragma unroll
            for (int i = 0; i < 8; i++) a[i] = sF1[(ty * 8 + i) * 256 + k0 + kk];
            float4 b = *(const float4*)(sB2 + kk * 128 + tx * 4);
#pragma unroll
            for (int i = 0; i < 8; i++) {
                acc2[i][0] = fmaf(a[i], b.x, acc2[i][0]);
                acc2[i][1] = fmaf(a[i], b.y, acc2[i][1]);
                acc2[i][2] = fmaf(a[i], b.z, acc2[i][2]);
                acc2[i][3] = fmaf(a[i], b.w, acc2[i][3]);
            }
        }
    }
    {
        int c0 = tx * 4;
        float4 bv = *(const float4*)(bf2 + c0);
#pragma unroll
        for (int i = 0; i < 8; i++) {
            int r = ty * 8 + i;
            int n = n0 + r;
            if (n < NN) {
                float4 o;
                o.x = sOut[r * 128 + c0 + 0] + acc2[i][0] + bv.x;
                o.y = sOut[r * 128 + c0 + 1] + acc2[i][1] + bv.y;
                o.z = sOut[r * 128 + c0 + 2] + acc2[i][2] + bv.z;
                o.w = sOut[r * 128 + c0 + 3] + acc2[i][3] + bv.w;
                *(float4*)(outp + (size_t)n * H + c0) = o;
            }
        }
    }
}

// ===========================================================================
extern "C" void kernel_launch(void* const* d_in, const int* in_sizes, int n_in,
                              void* d_out, int out_size) {
    const float* x     = (const float*)d_in[0];
    const int*   esrc  = (const int*)d_in[1];
    const int*   edst  = (const int*)d_in[2];
    const float* emb   = (const float*)d_in[3];
    const float* ln1g  = (const float*)d_in[4];
    const float* ln1b  = (const float*)d_in[5];
    const float* Wself = (const float*)d_in[6];
    const float* bself = (const float*)d_in[7];
    const float* Wm1   = (const float*)d_in[8];
    const float* bm1   = (const float*)d_in[9];
    const float* Wm2   = (const float*)d_in[10];
    const float* bm2   = (const float*)d_in[11];
    const float* Wg1   = (const float*)d_in[12];
    const float* bg1   = (const float*)d_in[13];
    const float* Wg2   = (const float*)d_in[14];
    const float* bg2   = (const float*)d_in[15];
    const float* Wagg  = (const float*)d_in[16];
    const float* bagg  = (const float*)d_in[17];
    const float* ln2g  = (const float*)d_in[18];
    const float* ln2b  = (const float*)d_in[19];
    const float* Wf1   = (const float*)d_in[20];
    const float* bf1   = (const float*)d_in[21];
    const float* Wf2   = (const float*)d_in[22];
    const float* bf2   = (const float*)d_in[23];

    float* outp = (float*)d_out;
    float* erp  = outp + (size_t)NN * H;

    cudaFuncSetAttribute(edge_kernel, cudaFuncAttributeMaxDynamicSharedMemorySize,
                         F_TOTAL);
    cudaFuncSetAttribute(node_kernel, cudaFuncAttributeMaxDynamicSharedMemorySize,
                         NODE_SMEM_BYTES);

    zero_kernel<<<1024, 256>>>();
    ln1_kernel<<<(NN + 7) / 8, 256>>>(x, ln1g, ln1b);
    deg_kernel<<<(NE + 255) / 256, 256>>>(edst);
    edge_kernel<<<148, 384, F_TOTAL>>>(esrc, edst, emb, Wg1, bg1, Wg2, bg2,
                                       Wm1, bm1, Wm2, bm2, erp);
    node_kernel<<<(NN + 63) / 64, 256, NODE_SMEM_BYTES>>>(x, Wself, bself,
                                                          Wagg, bagg, ln2g, ln2b,
                                                          Wf1, bf1, Wf2, bf2, outp);
}

// round 14
// speedup vs baseline: 1.3417x; 1.0203x over previous
#include <cuda_runtime.h>
#include <cuda_bf16.h>
#include <cuda_fp16.h>
#include <math.h>
#include <stdint.h>

#define NN 50000
#define NE 600000
#define H  128
#define ED 64

// Scratch (no allocations allowed)
__device__ float g_h[NN * H];     // LN1(x)
__device__ float g_agg[NN * H];   // scatter-sum of edge_repr
__device__ float g_deg[NN];       // edge counts per dst
__device__ float g_gate[NE];      // gate scalar per edge

__device__ __forceinline__ float gelu_f(float x) { return x * normcdff(x); }

// ============================ mma helpers ==================================
__device__ __forceinline__ uint32_t smem_u32(const void* p) {
    uint32_t a;
    asm("{ .reg .u64 t; cvta.to.shared.u64 t, %1; cvt.u32.u64 %0, t; }"
        : "=r"(a) : "l"(p));
    return a;
}

__device__ __forceinline__ void mma_f16(float* c, const uint32_t* a, const uint32_t* b) {
    asm volatile("mma.sync.aligned.m16n8k16.row.col.f32.f16.f16.f32 "
        "{%0,%1,%2,%3}, {%4,%5,%6,%7}, {%8,%9}, {%0,%1,%2,%3};"
        : "+f"(c[0]), "+f"(c[1]), "+f"(c[2]), "+f"(c[3])
        : "r"(a[0]), "r"(a[1]), "r"(a[2]), "r"(a[3]), "r"(b[0]), "r"(b[1]));
}

__device__ __forceinline__ void ldm_x4(uint32_t& r0, uint32_t& r1, uint32_t& r2,
                                       uint32_t& r3, uint32_t addr) {
    asm volatile("ldmatrix.sync.aligned.m8n8.x4.shared.b16 {%0,%1,%2,%3}, [%4];"
        : "=r"(r0), "=r"(r1), "=r"(r2), "=r"(r3) : "r"(addr));
}

__device__ __forceinline__ uint32_t pack_h2(float a, float b) {
    __half2 t = __floats2half2_rn(a, b);
    return *reinterpret_cast<uint32_t*>(&t);
}

// ============================ simple kernels ===============================
__global__ void zero_kernel() {
    int idx = blockIdx.x * blockDim.x + threadIdx.x;
    int stride = gridDim.x * blockDim.x;
    for (int i = idx; i < NN * H; i += stride) g_agg[i] = 0.f;
    for (int i = idx; i < NN; i += stride) g_deg[i] = 0.f;
}

__global__ void ln1_kernel(const float* __restrict__ x,
                           const float* __restrict__ g,
                           const float* __restrict__ b) {
    int row = blockIdx.x * 8 + (threadIdx.x >> 5);
    if (row >= NN) return;
    int lane = threadIdx.x & 31;
    float v[4]; float s = 0.f;
#pragma unroll
    for (int i = 0; i < 4; i++) { v[i] = x[row * H + lane + 32 * i]; s += v[i]; }
#pragma unroll
    for (int o = 16; o; o >>= 1) s += __shfl_xor_sync(0xffffffffu, s, o);
    float mu = s * (1.f / H);
    float vs = 0.f;
#pragma unroll
    for (int i = 0; i < 4; i++) { float d = v[i] - mu; vs += d * d; }
#pragma unroll
    for (int o = 16; o; o >>= 1) vs += __shfl_xor_sync(0xffffffffu, vs, o);
    float rs = rsqrtf(vs * (1.f / H) + 1e-5f);
#pragma unroll
    for (int i = 0; i < 4; i++) {
        int c = lane + 32 * i;
        g_h[row * H + c] = (v[i] - mu) * rs * g[c] + b[c];
    }
}

__global__ void deg_kernel(const int* __restrict__ dst) {
    int i = blockIdx.x * blockDim.x + threadIdx.x;
    if (i < NE) atomicAdd(&g_deg[dst[i]], 1.f);
}

// ============================ gate edge kernel =============================
// 384 threads, 192-edge tiles, 12 warps = 6M x 2N. (round-7, best measured)
#define G_SRC   0
#define G_DST   768
#define G_ACC   1536
#define G_BG1   2304
#define G_WG2   2816
#define G_WH    3328
#define G_A0    (G_WH + 83968)
#define G_A1    (G_A0 + 27648)
#define G_TOTAL (G_A1 + 27648)
#define G_NT    3125

__global__ __launch_bounds__(384, 1) void gate_edge_kernel(
    const int* __restrict__ esrc, const int* __restrict__ edst,
    const float* __restrict__ emb,
    const float* __restrict__ Wg1, const float* __restrict__ bg1,
    const float* __restrict__ Wg2, const float* __restrict__ bg2)
{
    extern __shared__ char sm[];
    int tid = threadIdx.x, lane = tid & 31, wid = tid >> 5;
    int warp_m = wid >> 1, warp_n = wid & 1;
    int* sSrc = (int*)(sm + G_SRC);
    int* sDst = (int*)(sm + G_DST);
    float* sAcc = (float*)(sm + G_ACC);
    float* sBg1 = (float*)(sm + G_BG1);
    float* sWg2 = (float*)(sm + G_WG2);
    uint32_t sb = smem_u32(sm);

    if (tid < 128) { sBg1[tid] = bg1[tid]; sWg2[tid] = Wg2[tid]; }
    for (int idx = tid; idx < 320 * 128; idx += 384) {
        int k = idx >> 7, n = idx & 127;
        ((__half*)(sm + G_WH))[n * 328 + k] = __float2half_rn(Wg1[idx]);
    }
    __syncthreads();
    float bg2v = bg2[0];

    int rr = lane & 7, grp = lane >> 3;
    uint32_t aA_rel = (uint32_t)(warp_m * 32 + rr + (grp & 1) * 8) * 144
                    + (uint32_t)(grp >> 1) * 16;
    uint32_t aB = sb + G_WH + (uint32_t)(warp_n * 64 + rr + (grp >> 1) * 8) * 656
                + (uint32_t)(grp & 1) * 16;

    int prow = tid >> 4, pkq = tid & 15;

    for (int t = blockIdx.x; t < G_NT; t += gridDim.x) {
        int e0 = t * 192;
        if (tid < 192) {
            int e = e0 + tid;
            sSrc[tid] = esrc[e]; sDst[tid] = edst[e];
        }
        __syncthreads();

        float acc[2][8][4];
#pragma unroll
        for (int i = 0; i < 2; i++)
#pragma unroll
            for (int j = 0; j < 8; j++)
#pragma unroll
                for (int q = 0; q < 4; q++) acc[i][j][q] = 0.f;

        float4 pf[8];
#pragma unroll
        for (int it = 0; it < 8; it++) {
            int row = prow + it * 24;
            pf[it] = ((const float4*)(g_h + (size_t)sDst[row] * H))[pkq];
        }

#pragma unroll 1
        for (int c = 0; c < 5; c++) {
            uint32_t abase = (c & 1) ? (uint32_t)G_A1 : (uint32_t)G_A0;
            char* smA = sm + abase;
#pragma unroll
            for (int it = 0; it < 8; it++) {
                int row = prow + it * 24;
                uint32_t h0 = pack_h2(pf[it].x, pf[it].y);
                uint32_t h1 = pack_h2(pf[it].z, pf[it].w);
                *(uint2*)(smA + row * 144 + pkq * 8) = make_uint2(h0, h1);
            }
            if (c < 4) {
                int cn = c + 1;
#pragma unroll
                for (int it = 0; it < 8; it++) {
                    int row = prow + it * 24;
                    const float* p;
                    if (cn == 1)      p = g_h + (size_t)sDst[row] * H + 64;
                    else if (cn == 2) p = g_h + (size_t)sSrc[row] * H;
                    else if (cn == 3) p = g_h + (size_t)sSrc[row] * H + 64;
                    else              p = emb + (size_t)(e0 + row) * ED;
                    pf[it] = ((const float4*)p)[pkq];
                }
            }
            __syncthreads();
            uint32_t aA = sb + abase + aA_rel;
            uint32_t kgb = (uint32_t)c << 7;
#pragma unroll
            for (int kk = 0; kk < 4; kk++) {
                uint32_t ah[2][4], bh[8][2];
#pragma unroll
                for (int mt = 0; mt < 2; mt++) {
                    uint32_t ad = aA + mt * (16 * 144) + kk * 32;
                    ldm_x4(ah[mt][0], ah[mt][1], ah[mt][2], ah[mt][3], ad);
                }
#pragma unroll
                for (int p4 = 0; p4 < 4; p4++) {
                    uint32_t bd = aB + p4 * (16 * 656) + kgb + kk * 32;
                    ldm_x4(bh[2 * p4][0], bh[2 * p4][1],
                           bh[2 * p4 + 1][0], bh[2 * p4 + 1][1], bd);
                }
#pragma unroll
                for (int mt = 0; mt < 2; mt++)
#pragma unroll
                    for (int nt = 0; nt < 8; nt++)
                        mma_f16(acc[mt][nt], ah[mt], bh[nt]);
            }
            __syncthreads();
        }

        if (tid < 192) sAcc[tid] = 0.f;
        __syncthreads();
#pragma unroll
        for (int mt = 0; mt < 2; mt++)
#pragma unroll
            for (int rh = 0; rh < 2; rh++) {
                int R = warp_m * 32 + mt * 16 + (lane >> 2) + rh * 8;
                float part = 0.f;
#pragma unroll
                for (int nt = 0; nt < 8; nt++) {
                    int C0 = warp_n * 64 + nt * 8 + (lane & 3) * 2;
                    part += gelu_f(acc[mt][nt][rh * 2 + 0] + sBg1[C0]) * sWg2[C0];
                    part += gelu_f(acc[mt][nt][rh * 2 + 1] + sBg1[C0 + 1]) * sWg2[C0 + 1];
                }
                part += __shfl_xor_sync(0xffffffffu, part, 1);
                part += __shfl_xor_sync(0xffffffffu, part, 2);
                if ((lane & 3) == 0) atomicAdd(&sAcc[R], part);
            }
        __syncthreads();
        if (tid < 192) {
            g_gate[e0 + tid] = 1.f / (1.f + expf(-(sAcc[tid] + bg2v)));
        }
        __syncthreads();
    }
}

// ============================ msg edge kernel (192-edge tiles) =============
// 384 threads, 192-edge tiles (600000 = 192*3125), 12 warps = 6M x 2N.
// Warp tile 32x64 for both GEMMs.
#define M_SRC   0                     // 192 ints = 768
#define M_DST   768
#define M_BM1   1536
#define M_BM2   2048
#define M_W1H   2560                  // 128 x 200 fp16 (400B stride) = 51200
#define M_W2H   (M_W1H + 51200)       // 128 x 136 fp16 (272B stride) = 34816
#define M_UN    (M_W2H + 34816)       // 88576 union region
#define M_A10   (M_UN)                // A buf0: 192 x 72 fp16 (144B) = 27648
#define M_A11   (M_UN + 27648)        // A buf1
#define M_HH    (M_UN)                // H: 192 x 136 fp16 (272B) = 52224
#define M_TOTAL (M_UN + 55296)        // 143872
#define M_NT    3125

__global__ __launch_bounds__(384, 1) void msg_edge_kernel(
    const int* __restrict__ esrc, const int* __restrict__ edst,
    const float* __restrict__ emb,
    const float* __restrict__ Wm1, const float* __restrict__ bm1,
    const float* __restrict__ Wm2, const float* __restrict__ bm2,
    float* __restrict__ er_out)
{
    extern __shared__ char sm[];
    int tid = threadIdx.x, lane = tid & 31, wid = tid >> 5;
    int warp_m = wid >> 1, warp_n = wid & 1;   // warp_m 0..5, warp_n 0..1
    int* sSrc = (int*)(sm + M_SRC);
    int* sDst = (int*)(sm + M_DST);
    float* sBm1 = (float*)(sm + M_BM1);
    float* sBm2 = (float*)(sm + M_BM2);
    uint32_t sb = smem_u32(sm);

    if (tid < 128) { sBm1[tid] = bm1[tid]; sBm2[tid] = bm2[tid]; }
    for (int idx = tid; idx < 192 * 128; idx += 384) {
        int k = idx >> 7, n = idx & 127;
        ((__half*)(sm + M_W1H))[n * 200 + k] = __float2half_rn(Wm1[idx]);
    }
    for (int idx = tid; idx < 128 * 128; idx += 384) {
        int k = idx >> 7, n = idx & 127;
        ((__half*)(sm + M_W2H))[n * 136 + k] = __float2half_rn(Wm2[idx]);
    }
    __syncthreads();

    int rr = lane & 7, grp = lane >> 3;
    uint32_t aA1_rel = (uint32_t)(warp_m * 32 + rr + (grp & 1) * 8) * 144
                     + (uint32_t)(grp >> 1) * 16;
    uint32_t aH_rel = (uint32_t)(warp_m * 32 + rr + (grp & 1) * 8) * 272
                    + (uint32_t)(grp >> 1) * 16;
    uint32_t aW1 = sb + M_W1H + (uint32_t)(warp_n * 64 + rr + (grp >> 1) * 8) * 400
                 + (uint32_t)(grp & 1) * 16;
    uint32_t aW2 = sb + M_W2H + (uint32_t)(warp_n * 64 + rr + (grp >> 1) * 8) * 272
                 + (uint32_t)(grp & 1) * 16;

    int prow = tid >> 4, pkq = tid & 15;   // rows prow + it*24, it 0..7

    for (int t = blockIdx.x; t < M_NT; t += gridDim.x) {
        int e0 = t * 192;
        if (tid < 192) { sSrc[tid] = esrc[e0 + tid]; sDst[tid] = edst[e0 + tid]; }
        __syncthreads();

        float acc1[2][8][4];
#pragma unroll
        for (int i = 0; i < 2; i++)
#pragma unroll
            for (int j = 0; j < 8; j++)
#pragma unroll
                for (int q = 0; q < 4; q++) acc1[i][j][q] = 0.f;

        float4 pf[8];
#pragma unroll
        for (int it = 0; it < 8; it++) {
            int row = prow + it * 24;
            pf[it] = ((const float4*)(g_h + (size_t)sSrc[row] * H))[pkq];
        }

#pragma unroll 1
        for (int c = 0; c < 3; c++) {
            uint32_t abase = (c & 1) ? (uint32_t)M_A11 : (uint32_t)M_A10;
            char* smA = sm + abase;
#pragma unroll
            for (int it = 0; it < 8; it++) {
                int row = prow + it * 24;
                uint32_t h0 = pack_h2(pf[it].x, pf[it].y);
                uint32_t h1 = pack_h2(pf[it].z, pf[it].w);
                *(uint2*)(smA + row * 144 + pkq * 8) = make_uint2(h0, h1);
            }
            if (c < 2) {
                int cn = c + 1;
#pragma unroll
                for (int it = 0; it < 8; it++) {
                    int row = prow + it * 24;
                    const float* p;
                    if (cn == 1) p = g_h + (size_t)sSrc[row] * H + 64;
                    else         p = emb + (size_t)(e0 + row) * ED;
                    pf[it] = ((const float4*)p)[pkq];
                }
            }
            __syncthreads();
            uint32_t aA1 = sb + abase + aA1_rel;
            uint32_t kgb = (uint32_t)c << 7;
#pragma unroll
            for (int kk = 0; kk < 4; kk++) {
                uint32_t ah[2][4], bh[8][2];
#pragma unroll
                for (int mt = 0; mt < 2; mt++) {
                    uint32_t ad = aA1 + mt * (16 * 144) + kk * 32;
                    ldm_x4(ah[mt][0], ah[mt][1], ah[mt][2], ah[mt][3], ad);
                }
#pragma unroll
                for (int p4 = 0; p4 < 4; p4++) {
                    uint32_t bd = aW1 + p4 * (16 * 400) + kgb + kk * 32;
                    ldm_x4(bh[2 * p4][0], bh[2 * p4][1],
                           bh[2 * p4 + 1][0], bh[2 * p4 + 1][1], bd);
                }
#pragma unroll
                for (int mt = 0; mt < 2; mt++)
#pragma unroll
                    for (int nt = 0; nt < 8; nt++)
                        mma_f16(acc1[mt][nt], ah[mt], bh[nt]);
            }
            __syncthreads();
        }

        // gelu -> sH (fp16); H region overlaps dead A buffers (post-sync)
#pragma unroll
        for (int mt = 0; mt < 2; mt++)
#pragma unroll
            for (int nt = 0; nt < 8; nt++)
#pragma unroll
                for (int rh = 0; rh < 2; rh++) {
                    int R = warp_m * 32 + mt * 16 + (lane >> 2) + rh * 8;
                    int C0 = warp_n * 64 + nt * 8 + (lane & 3) * 2;
                    float v0 = gelu_f(acc1[mt][nt][rh * 2 + 0] + sBm1[C0]);
                    float v1 = gelu_f(acc1[mt][nt][rh * 2 + 1] + sBm1[C0 + 1]);
                    *(uint32_t*)(sm + M_HH + R * 272 + C0 * 2) = pack_h2(v0, v1);
                }
        __syncthreads();

        // prefetch gate + dst for epilogue (overlaps with GEMM2)
        float gv[2][2]; int dnv[2][2];
#pragma unroll
        for (int mt = 0; mt < 2; mt++)
#pragma unroll
            for (int rh = 0; rh < 2; rh++) {
                int R = warp_m * 32 + mt * 16 + (lane >> 2) + rh * 8;
                gv[mt][rh] = g_gate[e0 + R];
                dnv[mt][rh] = sDst[R];
            }

        float acc2[2][8][4];
#pragma unroll
        for (int i = 0; i < 2; i++)
#pragma unroll
            for (int j = 0; j < 8; j++)
#pragma unroll
                for (int q = 0; q < 4; q++) acc2[i][j][q] = 0.f;

        uint32_t aH = sb + (uint32_t)M_HH + aH_rel;
#pragma unroll
        for (int kk = 0; kk < 8; kk++) {
            uint32_t ah[2][4], bh[8][2];
#pragma unroll
            for (int mt = 0; mt < 2; mt++) {
                uint32_t ad = aH + mt * (16 * 272) + kk * 32;
                ldm_x4(ah[mt][0], ah[mt][1], ah[mt][2], ah[mt][3], ad);
            }
#pragma unroll
            for (int p4 = 0; p4 < 4; p4++) {
                uint32_t bd = aW2 + p4 * (16 * 272) + kk * 32;
                ldm_x4(bh[2 * p4][0], bh[2 * p4][1],
                       bh[2 * p4 + 1][0], bh[2 * p4 + 1][1], bd);
            }
#pragma unroll
            for (int mt = 0; mt < 2; mt++)
#pragma unroll
                for (int nt = 0; nt < 8; nt++)
                    mma_f16(acc2[mt][nt], ah[mt], bh[nt]);
        }

        // epilogue: er = gate * (D2 + bm2); store + scatter
#pragma unroll
        for (int mt = 0; mt < 2; mt++)
#pragma unroll
            for (int rh = 0; rh < 2; rh++) {
                int R = warp_m * 32 + mt * 16 + (lane >> 2) + rh * 8;
                int e = e0 + R;
                float gvv = gv[mt][rh];
                int dn = dnv[mt][rh];
#pragma unroll
                for (int nt = 0; nt < 8; nt++) {
                    int C0 = warp_n * 64 + nt * 8 + (lane & 3) * 2;
                    float o0 = gvv * (acc2[mt][nt][rh * 2 + 0] + sBm2[C0]);
                    float o1 = gvv * (acc2[mt][nt][rh * 2 + 1] + sBm2[C0 + 1]);
                    float2 ov = make_float2(o0, o1);
                    *(float2*)(er_out + (size_t)e * H + C0) = ov;
                    asm volatile("red.global.add.v2.f32 [%0], {%1,%2};"
                                 :: "l"(g_agg + (size_t)dn * H + C0),
                                    "f"(o0), "f"(o1) : "memory");
                }
            }
        __syncthreads();
    }
}

// ============================ node kernel (fp32, roofline) =================
#define NODE_SMEM_BYTES (49216 * 4)

__global__ __launch_bounds__(256, 1) void node_kernel(
    const float* __restrict__ x,
    const float* __restrict__ Wself, const float* __restrict__ bself,
    const float* __restrict__ Wagg,  const float* __restrict__ bagg,
    const float* __restrict__ ln2g,  const float* __restrict__ ln2b,
    const float* __restrict__ Wf1,   const float* __restrict__ bf1,
    const float* __restrict__ Wf2,   const float* __restrict__ bf2,
    float* __restrict__ outp)
{
    extern __shared__ float smf[];
    float* sAh  = smf;
    float* sAa  = sAh + 2048;
    float* sB   = sAa + 2048;
    float* sB2  = sB + 8192;
    float* sOut = sB2 + 4096;
    float* sLn  = sOut + 8192;
    float* sF1  = sLn + 8192;
    float* sInv = sF1 + 16384;

    int tid = threadIdx.x;
    int tx = tid & 31, ty = tid >> 5;
    int n0 = blockIdx.x * 64;

    if (tid < 64) {
        int n = n0 + tid;
        float d = (n < NN) ? g_deg[n] : 1.f;
        sInv[tid] = 1.f / fmaxf(d, 1.f);
    }

    float acc[8][4];
#pragma unroll
    for (int i = 0; i < 8; i++)
#pragma unroll
        for (int j = 0; j < 4; j++) acc[i][j] = 0.f;

    for (int k0 = 0; k0 < 128; k0 += 32) {
        __syncthreads();
#pragma unroll
        for (int i = 0; i < 8; i++) {
            int lin = tid + i * 256;
            int e = lin >> 5, k = lin & 31;
            int n = n0 + e; if (n >= NN) n = NN - 1;
            sAh[e * 32 + k] = g_h[n * H + k0 + k];
            sAa[e * 32 + k] = g_agg[n * H + k0 + k] * sInv[e];
        }
#pragma unroll
        for (int i = 0; i < 16; i++) {
            int lin = tid + i * 256;
            int kk = lin >> 7, c = lin & 127;
            sB[kk * 128 + c]  = Wself[(k0 + kk) * 128 + c];
            sB2[kk * 128 + c] = Wagg[(k0 + kk) * 128 + c];
        }
        __syncthreads();
#pragma unroll 4
        for (int kk = 0; kk < 32; kk++) {
            float ah[8], aa[8];
#pragma unroll
            for (int i = 0; i < 8; i++) {
                ah[i] = sAh[(ty * 8 + i) * 32 + kk];
                aa[i] = sAa[(ty * 8 + i) * 32 + kk];
            }
            float4 bs = *(const float4*)(sB + kk * 128 + tx * 4);
            float4 ba = *(const float4*)(sB2 + kk * 128 + tx * 4);
#pragma unroll
            for (int i = 0; i < 8; i++) {
                acc[i][0] = fmaf(ah[i], bs.x, fmaf(aa[i], ba.x, acc[i][0]));
                acc[i][1] = fmaf(ah[i], bs.y, fmaf(aa[i], ba.y, acc[i][1]));
                acc[i][2] = fmaf(ah[i], bs.z, fmaf(aa[i], ba.z, acc[i][2]));
                acc[i][3] = fmaf(ah[i], bs.w, fmaf(aa[i], ba.w, acc[i][3]));
            }
        }
    }

    {
        int c0 = tx * 4;
        float4 b1 = *(const float4*)(bself + c0);
        float4 b2 = *(const float4*)(bagg + c0);
#pragma unroll
        for (int i = 0; i < 8; i++) {
            int r = ty * 8 + i;
            int n = n0 + r; if (n >= NN) n = NN - 1;
            float4 xv = *(const float4*)(x + (size_t)n * H + c0);
            float4 o;
            o.x = xv.x + acc[i][0] + b1.x + b2.x;
            o.y = xv.y + acc[i][1] + b1.y + b2.y;
            o.z = xv.z + acc[i][2] + b1.z + b2.z;
            o.w = xv.w + acc[i][3] + b1.w + b2.w;
            *(float4*)(sOut + r * 128 + c0) = o;
        }
    }
    __syncthreads();

#pragma unroll
    for (int p = 0; p < 8; p++) {
        int r = ty * 8 + p;
        float v[4]; float s = 0.f;
#pragma unroll
        for (int i = 0; i < 4; i++) { v[i] = sOut[r * 128 + tx + 32 * i]; s += v[i]; }
#pragma unroll
        for (int o = 16; o; o >>= 1) s += __shfl_xor_sync(0xffffffffu, s, o);
        float mu = s * (1.f / H);
        float vs = 0.f;
#pragma unroll
        for (int i = 0; i < 4; i++) { float d = v[i] - mu; vs += d * d; }
#pragma unroll
        for (int o = 16; o; o >>= 1) vs += __shfl_xor_sync(0xffffffffu, vs, o);
        float rs = rsqrtf(vs * (1.f / H) + 1e-5f);
#pragma unroll
        for (int i = 0; i < 4; i++) {
            int c = tx + 32 * i;
            sLn[r * 128 + c] = (v[i] - mu) * rs * ln2g[c] + ln2b[c];
        }
    }

    float accF[8][8];
#pragma unroll
    for (int i = 0; i < 8; i++)
#pragma unroll
        for (int j = 0; j < 8; j++) accF[i][j] = 0.f;

    for (int k0 = 0; k0 < 128; k0 += 32) {
        __syncthreads();
#pragma unroll
        for (int i = 0; i < 32; i++) {
            int lin = tid + i * 256;
            int kk = lin >> 8, c = lin & 255;
            sB[kk * 256 + c] = Wf1[(k0 + kk) * 256 + c];
        }
        __syncthreads();
#pragma unroll 4
        for (int kk = 0; kk < 32; kk++) {
            float a[8];
#pragma unroll
            for (int i = 0; i < 8; i++) a[i] = sLn[(ty * 8 + i) * 128 + k0 + kk];
            float4 b0 = *(const float4*)(sB + kk * 256 + tx * 4);
            float4 b1v = *(const float4*)(sB + kk * 256 + 128 + tx * 4);
#pragma unroll
            for (int i = 0; i < 8; i++) {
                accF[i][0] = fmaf(a[i], b0.x, accF[i][0]);
                accF[i][1] = fmaf(a[i], b0.y, accF[i][1]);
                accF[i][2] = fmaf(a[i], b0.z, accF[i][2]);
                accF[i][3] = fmaf(a[i], b0.w, accF[i][3]);
                accF[i][4] = fmaf(a[i], b1v.x, accF[i][4]);
                accF[i][5] = fmaf(a[i], b1v.y, accF[i][5]);
                accF[i][6] = fmaf(a[i], b1v.z, accF[i][6]);
                accF[i][7] = fmaf(a[i], b1v.w, accF[i][7]);
            }
        }
    }
    {
        int c0a = tx * 4, c0b = 128 + tx * 4;
        float4 ba = *(const float4*)(bf1 + c0a);
        float4 bb = *(const float4*)(bf1 + c0b);
#pragma unroll
        for (int i = 0; i < 8; i++) {
            int r = ty * 8 + i;
            float4 fa, fb;
            fa.x = gelu_f(accF[i][0] + ba.x); fa.y = gelu_f(accF[i][1] + ba.y);
            fa.z = gelu_f(accF[i][2] + ba.z); fa.w = gelu_f(accF[i][3] + ba.w);
            fb.x = gelu_f(accF[i][4] + bb.x); fb.y = gelu_f(accF[i][5] + bb.y);
            fb.z = gelu_f(accF[i][6] + bb.z); fb.w = gelu_f(accF[i][7] + bb.w);
            *(float4*)(sF1 + r * 256 + c0a) = fa;
            *(float4*)(sF1 + r * 256 + c0b) = fb;
        }
    }
    __syncthreads();

    float acc2[8][4];
#pragma unroll
    for (int i = 0; i < 8; i++)
#pragma unroll
        for (int j = 0; j < 4; j++) acc2[i][j] = 0.f;

    for (int k0 = 0; k0 < 256; k0 += 32) {
        __syncthreads();
#pragma unroll
        for (int i = 0; i < 16; i++) {
            int lin = tid + i * 256;
            int kk = lin >> 7, c = lin & 127;
            sB2[kk * 128 + c] = Wf2[(k0 + kk) * 128 + c];
        }
        __syncthreads();
#pragma unroll 4
        for (int kk = 0; kk < 32; kk++) {
            float a[8];
#pragma unroll
            for (int i = 0; i < 8; i++) a[i] = sF1[(ty * 8 + i) * 256 + k0 + kk];
            float4 b = *(const float4*)(sB2 + kk * 128 + tx * 4);
#pragma unroll
            for (int i = 0; i < 8; i++) {
                acc2[i][0] = fmaf(a[i], b.x, acc2[i][0]);
                acc2[i][1] = fmaf(a[i], b.y, acc2[i][1]);
                acc2[i][2] = fmaf(a[i], b.z, acc2[i][2]);
                acc2[i][3] = fmaf(a[i], b.w, acc2[i][3]);
            }
        }
    }
    {
        int c0 = tx * 4;
        float4 bv = *(const float4*)(bf2 + c0);
#pragma unroll
        for (int i = 0; i < 8; i++) {
            int r = ty * 8 + i;
            int n = n0 + r;
            if (n < NN) {
                float4 o;
                o.x = sOut[r * 128 + c0 + 0] + acc2[i][0] + bv.x;
                o.y = sOut[r * 128 + c0 + 1] + acc2[i][1] + bv.y;
                o.z = sOut[r * 128 + c0 + 2] + acc2[i][2] + bv.z;
                o.w = sOut[r * 128 + c0 + 3] + acc2[i][3] + bv.w;
                *(float4*)(outp + (size_t)n * H + c0) = o;
            }
        }
    }
}

// ===========================================================================
extern "C" void kernel_launch(void* const* d_in, const int* in_sizes, int n_in,
                              void* d_out, int out_size) {
    const float* x     = (const float*)d_in[0];
    const int*   esrc  = (const int*)d_in[1];
    const int*   edst  = (const int*)d_in[2];
    const float* emb   = (const float*)d_in[3];
    const float* ln1g  = (const float*)d_in[4];
    const float* ln1b  = (const float*)d_in[5];
    const float* Wself = (const float*)d_in[6];
    const float* bself = (const float*)d_in[7];
    const float* Wm1   = (const float*)d_in[8];
    const float* bm1   = (const float*)d_in[9];
    const float* Wm2   = (const float*)d_in[10];
    const float* bm2   = (const float*)d_in[11];
    const float* Wg1   = (const float*)d_in[12];
    const float* bg1   = (const float*)d_in[13];
    const float* Wg2   = (const float*)d_in[14];
    const float* bg2   = (const float*)d_in[15];
    const float* Wagg  = (const float*)d_in[16];
    const float* bagg  = (const float*)d_in[17];
    const float* ln2g  = (const float*)d_in[18];
    const float* ln2b  = (const float*)d_in[19];
    const float* Wf1   = (const float*)d_in[20];
    const float* bf1   = (const float*)d_in[21];
    const float* Wf2   = (const float*)d_in[22];
    const float* bf2   = (const float*)d_in[23];

    float* outp = (float*)d_out;
    float* erp  = outp + (size_t)NN * H;

    cudaFuncSetAttribute(gate_edge_kernel, cudaFuncAttributeMaxDynamicSharedMemorySize,
                         G_TOTAL);
    cudaFuncSetAttribute(msg_edge_kernel, cudaFuncAttributeMaxDynamicSharedMemorySize,
                         M_TOTAL);
    cudaFuncSetAttribute(node_kernel, cudaFuncAttributeMaxDynamicSharedMemorySize,
                         NODE_SMEM_BYTES);

    zero_kernel<<<1024, 256>>>();
    ln1_kernel<<<(NN + 7) / 8, 256>>>(x, ln1g, ln1b);
    deg_kernel<<<(NE + 255) / 256, 256>>>(edst);
    gate_edge_kernel<<<148, 384, G_TOTAL>>>(esrc, edst, emb, Wg1, bg1, Wg2, bg2);
    msg_edge_kernel<<<148, 384, M_TOTAL>>>(esrc, edst, emb, Wm1, bm1, Wm2, bm2, erp);
    node_kernel<<<(NN + 63) / 64, 256, NODE_SMEM_BYTES>>>(x, Wself, bself,
                                                          Wagg, bagg, ln2g, ln2b,
                                                          Wf1, bf1, Wf2, bf2, outp);
}